// round 1
// baseline (speedup 1.0000x reference)
#include <cuda_runtime.h>
#include <math.h>

// ---------------------------------------------------------------------------
// HaplotypeEmbedding: fused gather-MLP.
//   Precompute  P[l][v][j] = sum_d tables[l][v][d] * W1[l*256+d][j]   (8 MB)
//   Per sample: h = gelu( sum_l P[l][tok_l] + b1 );  out = h @ W2 + b2
// ---------------------------------------------------------------------------

#define L_    8
#define V_    512
#define D_    256
#define HID_  512
#define NOUT_ 256
#define NTOT  131072          // B*K = 8192*16
#define MTILE 64
#define NBLK  (NTOT / MTILE)  // 2048

__device__ float g_P[L_ * V_ * HID_];   // 8.39 MB projected tables (scratch)
__device__ int   g_is64;                // haplotypes dtype flag

typedef unsigned long long u64;

__device__ __forceinline__ u64 pack2(float lo, float hi) {
    u64 r; asm("mov.b64 %0, {%1, %2};" : "=l"(r) : "f"(lo), "f"(hi)); return r;
}
__device__ __forceinline__ void unpack2(u64 v, float& lo, float& hi) {
    asm("mov.b64 {%0, %1}, %2;" : "=f"(lo), "=f"(hi) : "l"(v));
}
__device__ __forceinline__ void fma2(u64& c, u64 a, u64 b) {
    asm("fma.rn.f32x2 %0, %1, %2, %0;" : "+l"(c) : "l"(a), "l"(b));
}
__device__ __forceinline__ float gelu1(float x) {
    return 0.5f * x * (1.0f + erff(x * 0.70710678118654752440f));
}
__device__ __forceinline__ float4 add4(float4 a, float4 b) {
    return make_float4(a.x + b.x, a.y + b.y, a.z + b.z, a.w + b.w);
}
__device__ __forceinline__ float4 gelu4b(float4 a, float4 b) {
    return make_float4(gelu1(a.x + b.x), gelu1(a.y + b.y),
                       gelu1(a.z + b.z), gelu1(a.w + b.w));
}

// ---------------------------------------------------------------------------
// Detect int64 vs int32 haplotype layout (values are in [0,512), so if the
// buffer is little-endian int64, every odd 32-bit word is zero).
// ---------------------------------------------------------------------------
__global__ void detect_kernel(const unsigned int* __restrict__ w) {
    if (threadIdx.x == 0) {
        int ok = 1;
        for (int i = 0; i < 64; i++) ok &= (w[2 * i + 1] == 0u);
        g_is64 = ok;
    }
}

// ---------------------------------------------------------------------------
// Precompute P[l][v][:] = tables[l][v] @ W1_l.   Grid: 8*32 blocks, 512 thr.
// Block = (l, 16 v-rows); thread j computes 16 outputs.
// ---------------------------------------------------------------------------
__global__ void __launch_bounds__(512) precompute_kernel(
        const float* __restrict__ tables, const float* __restrict__ W1) {
    __shared__ float4 sT4[16 * 64];     // 16 rows x 256 floats = 16 KB
    const int l  = blockIdx.x >> 5;
    const int v0 = (blockIdx.x & 31) << 4;
    const int j  = threadIdx.x;

    const float4* tsrc = (const float4*)(tables + (l * V_ + v0) * D_);
    sT4[j]       = tsrc[j];
    sT4[j + 512] = tsrc[j + 512];
    __syncthreads();

    float acc[16];
#pragma unroll
    for (int r = 0; r < 16; r++) acc[r] = 0.f;

    const float* w1p = W1 + (l * D_) * HID_ + j;
#pragma unroll 4
    for (int dq = 0; dq < 64; dq++) {
        float w0 = w1p[(4 * dq + 0) * HID_];
        float w1 = w1p[(4 * dq + 1) * HID_];
        float w2 = w1p[(4 * dq + 2) * HID_];
        float w3 = w1p[(4 * dq + 3) * HID_];
#pragma unroll
        for (int r = 0; r < 16; r++) {
            float4 t = sT4[r * 64 + dq];
            acc[r] += w0 * t.x;
            acc[r] += w1 * t.y;
            acc[r] += w2 * t.z;
            acc[r] += w3 * t.w;
        }
    }
#pragma unroll
    for (int r = 0; r < 16; r++)
        g_P[(l * V_ + v0 + r) * HID_ + j] = acc[r];
}

// ---------------------------------------------------------------------------
// Main fused kernel: 64 samples per block, 256 threads.
// Phase 1: each warp gathers+sums 8 P rows per sample, bias+gelu -> sH[64][512]
// Phase 2: C[64,256] = H @ W2, fp32x2 packed FMA, m-paired accumulators.
// ---------------------------------------------------------------------------
#define SMEM_H_F    (MTILE * HID_)     // 32768 floats
#define SMEM_W2T_F  (16 * NOUT_)       // 4096 floats
#define SMEM_BYTES  ((SMEM_H_F + SMEM_W2T_F) * 4)   // 147456 bytes

__global__ void __launch_bounds__(256, 1) main_kernel(
        const unsigned int* __restrict__ hap,
        const float* __restrict__ b1,
        const float* __restrict__ W2,
        const float* __restrict__ b2,
        float* __restrict__ out) {
    extern __shared__ float smem[];
    float* sH  = smem;                  // [64][512] row-major
    float* sW2 = smem + SMEM_H_F;       // [16][256] k-tile of W2

    const int tid  = threadIdx.x;
    const int warp = tid >> 5;
    const int lane = tid & 31;
    const int base = blockIdx.x * MTILE;
    const int is64 = g_is64;

    // ------------------ Phase 1: gather + bias + gelu ------------------
    const float4* b1f4 = (const float4*)b1;
    float4 bv0 = b1f4[lane];
    float4 bv1 = b1f4[lane + 32];
    float4 bv2 = b1f4[lane + 64];
    float4 bv3 = b1f4[lane + 96];

    for (int s = 0; s < 8; s++) {
        const int m = (warp << 3) + s;
        const int n = base + m;
        int tok = 0;
        if (lane < 8)
            tok = is64 ? (int)hap[(n * 8 + lane) * 2] : (int)hap[n * 8 + lane];

        float4 a0 = make_float4(0.f, 0.f, 0.f, 0.f), a1 = a0, a2 = a0, a3 = a0;
#pragma unroll
        for (int l = 0; l < 8; l++) {
            int t = __shfl_sync(0xffffffffu, tok, l) & (V_ - 1);
            const float4* row = (const float4*)(g_P + ((l * V_ + t) << 9)) + lane;
            a0 = add4(a0, row[0]);
            a1 = add4(a1, row[32]);
            a2 = add4(a2, row[64]);
            a3 = add4(a3, row[96]);
        }
        float4* dH = (float4*)(sH + m * HID_);
        dH[lane]      = gelu4b(a0, bv0);
        dH[lane + 32] = gelu4b(a1, bv1);
        dH[lane + 64] = gelu4b(a2, bv2);
        dH[lane + 96] = gelu4b(a3, bv3);
    }
    __syncthreads();

    // ------------------ Phase 2: C = H @ W2 (f32x2 FMA) ------------------
    // Thread owns rows m0..m0+7 (m0 = warp*8), cols n = lane + 32*p (p<8).
    // Accumulators packed along m: acc[q][p] = (C[m0+2q][n_p], C[m0+2q+1][n_p])
    const int m0 = warp << 3;
    u64 acc[4][8];
#pragma unroll
    for (int q = 0; q < 4; q++)
#pragma unroll
        for (int p = 0; p < 8; p++) acc[q][p] = 0ull;

    const float4* W2f4 = (const float4*)W2;   // 64 float4 per row of 256
    float4 pre[4];
#pragma unroll
    for (int i = 0; i < 4; i++) pre[i] = W2f4[tid + 256 * i];

    for (int kt = 0; kt < 32; kt++) {
        float4* tile = (float4*)sW2;
#pragma unroll
        for (int i = 0; i < 4; i++) tile[tid + 256 * i] = pre[i];
        __syncthreads();
        if (kt + 1 < 32) {
#pragma unroll
            for (int i = 0; i < 4; i++)
                pre[i] = W2f4[(kt + 1) * 1024 + tid + 256 * i];
        }
#pragma unroll
        for (int kk = 0; kk < 16; kk++) {
            const float* hc = sH + (kt * 16 + kk);
            float av[8];
#pragma unroll
            for (int i = 0; i < 8; i++) av[i] = hc[(m0 + i) * HID_];  // broadcast LDS
            u64 ap[4];
#pragma unroll
            for (int q = 0; q < 4; q++) ap[q] = pack2(av[2 * q], av[2 * q + 1]);

            const float* brow = sW2 + kk * NOUT_ + lane;
#pragma unroll
            for (int p = 0; p < 8; p++) {
                float bw = brow[32 * p];        // conflict-free scalar LDS
                u64 bd = pack2(bw, bw);
                fma2(acc[0][p], ap[0], bd);
                fma2(acc[1][p], ap[1], bd);
                fma2(acc[2][p], ap[2], bd);
                fma2(acc[3][p], ap[3], bd);
            }
        }
        __syncthreads();
    }

    // ------------------ Epilogue: + b2, store ------------------
    float bb[8];
#pragma unroll
    for (int p = 0; p < 8; p++) bb[p] = b2[lane + 32 * p];
#pragma unroll
    for (int q = 0; q < 4; q++) {
        float* o0 = out + (long long)(base + m0 + 2 * q) * NOUT_ + lane;
        float* o1 = o0 + NOUT_;
#pragma unroll
        for (int p = 0; p < 8; p++) {
            float lo, hi;
            unpack2(acc[q][p], lo, hi);
            o0[32 * p] = lo + bb[p];
            o1[32 * p] = hi + bb[p];
        }
    }
}

// ---------------------------------------------------------------------------
extern "C" void kernel_launch(void* const* d_in, const int* in_sizes, int n_in,
                              void* d_out, int out_size) {
    const unsigned int* hap    = (const unsigned int*)d_in[0];
    const float*        tables = (const float*)d_in[1];
    const float*        W1     = (const float*)d_in[2];
    const float*        b1     = (const float*)d_in[3];
    const float*        W2     = (const float*)d_in[4];
    const float*        b2     = (const float*)d_in[5];
    float*              out    = (float*)d_out;

    cudaFuncSetAttribute(main_kernel,
                         cudaFuncAttributeMaxDynamicSharedMemorySize, SMEM_BYTES);

    detect_kernel<<<1, 32>>>(hap);
    precompute_kernel<<<L_ * 32, 512>>>(tables, W1);
    main_kernel<<<NBLK, 256, SMEM_BYTES>>>(hap, b1, W2, b2, out);
}

// round 3
// speedup vs baseline: 1.4178x; 1.4178x over previous
#include <cuda_runtime.h>
#include <math.h>
#include <stdint.h>

// ---------------------------------------------------------------------------
// HaplotypeEmbedding via legacy mma.sync (tf32), warp-specialized.
//   Precompute  P[l][v][j] = tables[l][v] @ W1_l      (8.4 MB, L2-resident)
//   Per block (128 samples), 16 k-chunks of 32:
//     producer warps (4): gather+sum P rows + b1 + gelu + cvt.tf32 -> A tile
//                         stage W2 chunk (cvt.tf32)                -> B tile
//     consumer warps (8): mma.sync m16n8k8 tf32, acc in fp32 regs
//   Epilogue: + b2 -> out.
// ---------------------------------------------------------------------------

#define L_    8
#define V_    512
#define D_    256
#define HID_  512
#define NOUT_ 256
#define NTOT  131072
#define MTILE 128
#define NBLK  (NTOT / MTILE)   // 1024
#define KCH   32
#define NCH   (HID_ / KCH)     // 16

#define SA_STRIDE 36           // floats; 36 mod 32 = 4 -> A-frag bank = lane
#define SB_STRIDE 264          // floats; 264 mod 32 = 8 -> B-frag conflict-free
#define SA_BUF    (MTILE * SA_STRIDE)   // 4608 floats
#define SB_BUF    (KCH * SB_STRIDE)     // 8448 floats

#define SM_TOK_B   0
#define SM_A_B     4096
#define SM_B_B     (4096 + 2 * SA_BUF * 4)             // 40960
#define SMEM_BYTES (SM_B_B + 2 * SB_BUF * 4)           // 108544

__device__ float g_P[L_ * V_ * HID_];
__device__ int   g_is64;

__device__ __forceinline__ float gelu1(float x) {
    return 0.5f * x * (1.0f + erff(x * 0.70710678118654752440f));
}
__device__ __forceinline__ float tf32r(float x) {
    uint32_t u;
    asm("cvt.rna.tf32.f32 %0, %1;" : "=r"(u) : "f"(x));
    return __uint_as_float(u);
}
__device__ __forceinline__ void mma_tf32(float* d, const uint32_t* a,
                                         uint32_t b0, uint32_t b1) {
    asm volatile(
        "mma.sync.aligned.m16n8k8.row.col.f32.tf32.tf32.f32 "
        "{%0,%1,%2,%3}, {%4,%5,%6,%7}, {%8,%9}, {%0,%1,%2,%3};"
        : "+f"(d[0]), "+f"(d[1]), "+f"(d[2]), "+f"(d[3])
        : "r"(a[0]), "r"(a[1]), "r"(a[2]), "r"(a[3]), "r"(b0), "r"(b1));
}

// ---------------------------------------------------------------------------
__global__ void detect_kernel(const unsigned int* __restrict__ w) {
    if (threadIdx.x == 0) {
        int ok = 1;
        for (int i = 0; i < 64; i++) ok &= (w[2 * i + 1] == 0u);
        g_is64 = ok;
    }
}

// P[l][v][:] = tables[l][v] @ W1_l   (proven in round 1)
__global__ void __launch_bounds__(512) precompute_kernel(
        const float* __restrict__ tables, const float* __restrict__ W1) {
    __shared__ float4 sT4[16 * 64];
    const int l  = blockIdx.x >> 5;
    const int v0 = (blockIdx.x & 31) << 4;
    const int j  = threadIdx.x;

    const float4* tsrc = (const float4*)(tables + (l * V_ + v0) * D_);
    sT4[j]       = tsrc[j];
    sT4[j + 512] = tsrc[j + 512];
    __syncthreads();

    float acc[16];
#pragma unroll
    for (int r = 0; r < 16; r++) acc[r] = 0.f;
    const float* w1p = W1 + (l * D_) * HID_ + j;
#pragma unroll 4
    for (int dq = 0; dq < 64; dq++) {
        float w0 = w1p[(4 * dq + 0) * HID_];
        float w1 = w1p[(4 * dq + 1) * HID_];
        float w2 = w1p[(4 * dq + 2) * HID_];
        float w3 = w1p[(4 * dq + 3) * HID_];
#pragma unroll
        for (int r = 0; r < 16; r++) {
            float4 t = sT4[r * 64 + dq];
            acc[r] += w0 * t.x; acc[r] += w1 * t.y;
            acc[r] += w2 * t.z; acc[r] += w3 * t.w;
        }
    }
#pragma unroll
    for (int r = 0; r < 16; r++)
        g_P[(l * V_ + v0 + r) * HID_ + j] = acc[r];
}

// ---------------------------------------------------------------------------
__global__ void __launch_bounds__(384, 1) main_kernel(
        const unsigned int* __restrict__ hap,
        const float* __restrict__ b1,
        const float* __restrict__ W2,
        const float* __restrict__ b2,
        float* __restrict__ out) {
    extern __shared__ char smem[];
    int*   sTok = (int*)(smem + SM_TOK_B);
    float* sA   = (float*)(smem + SM_A_B);
    float* sB   = (float*)(smem + SM_B_B);

    const int tid = threadIdx.x, warp = tid >> 5, lane = tid & 31;
    const int is64 = g_is64;

    // ---- tokens (clamped) ----
    for (int i = tid; i < MTILE * L_; i += 384) {
        long gi = (long)blockIdx.x * (MTILE * L_) + i;
        int v = is64 ? (int)hap[2 * gi] : (int)hap[gi];
        v = v < 0 ? 0 : (v > V_ - 1 ? V_ - 1 : v);
        sTok[i] = v;
    }
    __syncthreads();

    const bool producer = (warp >= 8);

    // consumer accumulators
    float acc[2][16][4];
    if (!producer) {
#pragma unroll
        for (int mt = 0; mt < 2; mt++)
#pragma unroll
            for (int j = 0; j < 16; j++)
#pragma unroll
                for (int q = 0; q < 4; q++) acc[mt][j][q] = 0.f;
    }

    const int wp = warp - 8;          // producer warp id 0..3
    const int r4 = lane >> 3, c = lane & 7;
    const int m0 = (warp >> 1) * 32;  // consumer row base
    const int n0 = (warp & 1) * 128;  // consumer col base

    // ---------------- producer chunk fill ----------------
    auto fill = [&](int kt, int buf) {
        // A: H[m][kt*32 .. +32) = gelu( sum_l P[l][tok] + b1 ), tf32
        float* A = sA + buf * SA_BUF;
        float4 b1v = __ldg(((const float4*)b1) + kt * 8 + c);
#pragma unroll 2
        for (int it = 0; it < 8; it++) {
            int m = wp * 32 + it * 4 + r4;
            const int* tk = sTok + m * L_;
            float4 a = make_float4(0.f, 0.f, 0.f, 0.f);
#pragma unroll
            for (int l = 0; l < L_; l++) {
                int t = tk[l];
                float4 v = __ldg(((const float4*)g_P) +
                                 ((l * V_ + t) << 7) + kt * 8 + c);
                a.x += v.x; a.y += v.y; a.z += v.z; a.w += v.w;
            }
            float4 g;
            g.x = tf32r(gelu1(a.x + b1v.x));
            g.y = tf32r(gelu1(a.y + b1v.y));
            g.z = tf32r(gelu1(a.z + b1v.z));
            g.w = tf32r(gelu1(a.w + b1v.w));
            *(float4*)(A + m * SA_STRIDE + c * 4) = g;
        }
        // B: W2[kt*32 .. +32)[0..256), tf32
        float* B = sB + buf * SB_BUF;
        int tp = wp * 32 + lane;      // 0..127
#pragma unroll
        for (int i = 0; i < 16; i++) {
            int e = i * 128 + tp;     // 0..2047
            int k = e >> 6, n4 = e & 63;
            float4 v = __ldg(((const float4*)W2) + (kt * KCH + k) * 64 + n4);
            v.x = tf32r(v.x); v.y = tf32r(v.y);
            v.z = tf32r(v.z); v.w = tf32r(v.w);
            *(float4*)(B + k * SB_STRIDE + n4 * 4) = v;
        }
    };

    // ---------------- consumer chunk mma ----------------
    auto consume = [&](int buf) {
        const float* A = sA + buf * SA_BUF;
        const float* B = sB + buf * SB_BUF;
#pragma unroll
        for (int ks = 0; ks < 4; ks++) {
            uint32_t a[2][4];
            const int acol = ks * 8 + (lane & 3);
#pragma unroll
            for (int mt = 0; mt < 2; mt++) {
                const float* Ab = A + (m0 + mt * 16 + (lane >> 2)) * SA_STRIDE;
                a[mt][0] = __float_as_uint(Ab[acol]);
                a[mt][1] = __float_as_uint(Ab[8 * SA_STRIDE + acol]);
                a[mt][2] = __float_as_uint(Ab[acol + 4]);
                a[mt][3] = __float_as_uint(Ab[8 * SA_STRIDE + acol + 4]);
            }
            const float* Bk = B + (ks * 8 + (lane & 3)) * SB_STRIDE +
                              n0 + (lane >> 2);
#pragma unroll
            for (int j = 0; j < 16; j++) {
                uint32_t b0 = __float_as_uint(Bk[8 * j]);
                uint32_t b1 = __float_as_uint(Bk[8 * j + 4 * SB_STRIDE]);
                mma_tf32(acc[0][j], a[0], b0, b1);
                mma_tf32(acc[1][j], a[1], b0, b1);
            }
        }
    };

    // ---------------- pipeline ----------------
    if (producer) fill(0, 0);
    __syncthreads();
    for (int kt = 0; kt < NCH; kt++) {
        if (producer) {
            if (kt + 1 < NCH) fill(kt + 1, (kt + 1) & 1);
        } else {
            consume(kt & 1);
        }
        __syncthreads();
    }

    // ---------------- epilogue ----------------
    if (!producer) {
        const float2* b2p = (const float2*)b2;
        float2* o2 = (float2*)out;
#pragma unroll
        for (int mt = 0; mt < 2; mt++) {
            size_t r0 = (size_t)blockIdx.x * MTILE + m0 + mt * 16 + (lane >> 2);
#pragma unroll
            for (int j = 0; j < 16; j++) {
                int cc = n0 / 2 + 4 * j + (lane & 3);
                float2 bv = __ldg(&b2p[cc]);
                float2 v0 = make_float2(acc[mt][j][0] + bv.x,
                                        acc[mt][j][1] + bv.y);
                float2 v1 = make_float2(acc[mt][j][2] + bv.x,
                                        acc[mt][j][3] + bv.y);
                o2[r0 * 128 + cc]       = v0;
                o2[(r0 + 8) * 128 + cc] = v1;
            }
        }
    }
}

// ---------------------------------------------------------------------------
extern "C" void kernel_launch(void* const* d_in, const int* in_sizes, int n_in,
                              void* d_out, int out_size) {
    const unsigned int* hap    = (const unsigned int*)d_in[0];
    const float*        tables = (const float*)d_in[1];
    const float*        W1     = (const float*)d_in[2];
    const float*        b1     = (const float*)d_in[3];
    const float*        W2     = (const float*)d_in[4];
    const float*        b2     = (const float*)d_in[5];
    float*              out    = (float*)d_out;

    cudaFuncSetAttribute(main_kernel,
                         cudaFuncAttributeMaxDynamicSharedMemorySize, SMEM_BYTES);

    detect_kernel<<<1, 32>>>(hap);
    precompute_kernel<<<L_ * 32, 512>>>(tables, W1);
    main_kernel<<<NBLK, 384, SMEM_BYTES>>>(hap, b1, W2, b2, out);
}

// round 4
// speedup vs baseline: 2.5433x; 1.7939x over previous
#include <cuda_runtime.h>
#include <math.h>
#include <stdint.h>

// ---------------------------------------------------------------------------
// HaplotypeEmbedding via mma.sync tf32, all-warp cooperative, occ 2.
//   P[l][v][:] = tables[l][v] @ W1_l  (8.4 MB, L2-resident)
//   Block = 64 samples; 16 k-chunks of 32:
//     all 8 warps: gather+sum P + b1 + gelu + tf32 -> A[64][32] smem
//                  stage W2 chunk (tf32)          -> B[32][256] smem
//     all 8 warps: mma m16n8k8 (warp tile 32x64), acc 64 regs fp32
// ---------------------------------------------------------------------------

#define L_    8
#define V_    512
#define D_    256
#define HID_  512
#define NOUT_ 256
#define NTOT  131072
#define MTILE 64
#define NBLK  (NTOT / MTILE)   // 2048
#define KCH   32
#define NCH   (HID_ / KCH)     // 16

#define SA_STRIDE 36           // 36 mod 32 = 4 -> a-frag LDS conflict-free
#define SB_STRIDE 264          // 264 mod 32 = 8 -> b-frag LDS conflict-free

__device__ float g_P[L_ * V_ * HID_];
__device__ int   g_is64;

__device__ __forceinline__ float gelu1(float x) {
    return 0.5f * x * (1.0f + erff(x * 0.70710678118654752440f));
}
__device__ __forceinline__ float tf32r(float x) {
    uint32_t u;
    asm("cvt.rna.tf32.f32 %0, %1;" : "=r"(u) : "f"(x));
    return __uint_as_float(u);
}
__device__ __forceinline__ void mma_tf32(float* d, const uint32_t* a,
                                         uint32_t b0, uint32_t b1) {
    asm volatile(
        "mma.sync.aligned.m16n8k8.row.col.f32.tf32.tf32.f32 "
        "{%0,%1,%2,%3}, {%4,%5,%6,%7}, {%8,%9}, {%0,%1,%2,%3};"
        : "+f"(d[0]), "+f"(d[1]), "+f"(d[2]), "+f"(d[3])
        : "r"(a[0]), "r"(a[1]), "r"(a[2]), "r"(a[3]), "r"(b0), "r"(b1));
}

// ---------------------------------------------------------------------------
__global__ void detect_kernel(const unsigned int* __restrict__ w) {
    if (threadIdx.x == 0) {
        int ok = 1;
        for (int i = 0; i < 64; i++) ok &= (w[2 * i + 1] == 0u);
        g_is64 = ok;
    }
}

__global__ void __launch_bounds__(512) precompute_kernel(
        const float* __restrict__ tables, const float* __restrict__ W1) {
    __shared__ float4 sT4[16 * 64];
    const int l  = blockIdx.x >> 5;
    const int v0 = (blockIdx.x & 31) << 4;
    const int j  = threadIdx.x;

    const float4* tsrc = (const float4*)(tables + (l * V_ + v0) * D_);
    sT4[j]       = tsrc[j];
    sT4[j + 512] = tsrc[j + 512];
    __syncthreads();

    float acc[16];
#pragma unroll
    for (int r = 0; r < 16; r++) acc[r] = 0.f;
    const float* w1p = W1 + (l * D_) * HID_ + j;
#pragma unroll 4
    for (int dq = 0; dq < 64; dq++) {
        float w0 = w1p[(4 * dq + 0) * HID_];
        float w1 = w1p[(4 * dq + 1) * HID_];
        float w2 = w1p[(4 * dq + 2) * HID_];
        float w3 = w1p[(4 * dq + 3) * HID_];
#pragma unroll
        for (int r = 0; r < 16; r++) {
            float4 t = sT4[r * 64 + dq];
            acc[r] += w0 * t.x; acc[r] += w1 * t.y;
            acc[r] += w2 * t.z; acc[r] += w3 * t.w;
        }
    }
#pragma unroll
    for (int r = 0; r < 16; r++)
        g_P[(l * V_ + v0 + r) * HID_ + j] = acc[r];
}

// ---------------------------------------------------------------------------
__global__ void __launch_bounds__(256, 2) main_kernel(
        const unsigned int* __restrict__ hap,
        const float* __restrict__ b1,
        const float* __restrict__ W2,
        const float* __restrict__ b2,
        float* __restrict__ out) {
    __shared__ int   sTok[MTILE * L_];                 // 2 KB
    __shared__ float sA[MTILE * SA_STRIDE];            // 9 KB
    __shared__ float sB[KCH * SB_STRIDE];              // 33 KB

    const int tid = threadIdx.x, warp = tid >> 5, lane = tid & 31;
    const int is64 = g_is64;

    // tokens (clamped)
    {
        long gbase = (long)blockIdx.x * (MTILE * L_);
#pragma unroll
        for (int i = 0; i < 2; i++) {
            int idx = tid + 256 * i;
            long gi = gbase + idx;
            int v = is64 ? (int)hap[2 * gi] : (int)hap[gi];
            v = v < 0 ? 0 : (v > V_ - 1 ? V_ - 1 : v);
            sTok[idx] = v;
        }
    }

    float acc[2][8][4];
#pragma unroll
    for (int mt = 0; mt < 2; mt++)
#pragma unroll
        for (int j = 0; j < 8; j++)
#pragma unroll
            for (int q = 0; q < 4; q++) acc[mt][j][q] = 0.f;

    const int c  = lane & 7;            // f4 column within chunk (0..7)
    const int r  = lane >> 3;           // row sub-index (0..3)
    const int m0 = (warp >> 2) * 32;    // consumer row base (0/32)
    const int n0 = (warp & 3) * 64;     // consumer col base

    __syncthreads();

    for (int kt = 0; kt < NCH; kt++) {
        // ---------------- produce: A = gelu(gather + b1), B = W2 chunk ----
        float4 b1v = __ldg(((const float4*)b1) + kt * 8 + c);
#pragma unroll
        for (int it = 0; it < 2; it++) {
            int m = it * 32 + warp * 4 + r;
            const int* tk = sTok + m * L_;
            float4 a = make_float4(0.f, 0.f, 0.f, 0.f);
#pragma unroll
            for (int l = 0; l < L_; l++) {
                float4 v = __ldg(((const float4*)g_P) +
                                 ((l * V_ + tk[l]) << 7) + kt * 8 + c);
                a.x += v.x; a.y += v.y; a.z += v.z; a.w += v.w;
            }
            float4 g;
            g.x = tf32r(gelu1(a.x + b1v.x));
            g.y = tf32r(gelu1(a.y + b1v.y));
            g.z = tf32r(gelu1(a.z + b1v.z));
            g.w = tf32r(gelu1(a.w + b1v.w));
            *(float4*)(sA + m * SA_STRIDE + c * 4) = g;
        }
#pragma unroll
        for (int i = 0; i < 8; i++) {
            int e = i * 256 + tid;
            int k = e >> 6, n4 = e & 63;
            float4 v = __ldg(((const float4*)W2) + (kt * KCH + k) * 64 + n4);
            v.x = tf32r(v.x); v.y = tf32r(v.y);
            v.z = tf32r(v.z); v.w = tf32r(v.w);
            *(float4*)(sB + k * SB_STRIDE + n4 * 4) = v;
        }
        __syncthreads();

        // ---------------- consume: warp tile 32x64 ----------------
#pragma unroll
        for (int ks = 0; ks < 4; ks++) {
            uint32_t a[2][4];
            const int acol = ks * 8 + (lane & 3);
#pragma unroll
            for (int mt = 0; mt < 2; mt++) {
                const float* Ab = sA + (m0 + mt * 16 + (lane >> 2)) * SA_STRIDE;
                a[mt][0] = __float_as_uint(Ab[acol]);
                a[mt][1] = __float_as_uint(Ab[8 * SA_STRIDE + acol]);
                a[mt][2] = __float_as_uint(Ab[acol + 4]);
                a[mt][3] = __float_as_uint(Ab[8 * SA_STRIDE + acol + 4]);
            }
            const float* Bk = sB + (ks * 8 + (lane & 3)) * SB_STRIDE +
                              n0 + (lane >> 2);
#pragma unroll
            for (int j = 0; j < 8; j++) {
                uint32_t b0 = __float_as_uint(Bk[8 * j]);
                uint32_t b1r = __float_as_uint(Bk[8 * j + 4 * SB_STRIDE]);
                mma_tf32(acc[0][j], a[0], b0, b1r);
                mma_tf32(acc[1][j], a[1], b0, b1r);
            }
        }
        __syncthreads();
    }

    // ---------------- epilogue: + b2, store ----------------
    const float2* b2p = (const float2*)b2;
    float2* o2 = (float2*)out;
#pragma unroll
    for (int mt = 0; mt < 2; mt++) {
        size_t r0 = (size_t)blockIdx.x * MTILE + m0 + mt * 16 + (lane >> 2);
#pragma unroll
        for (int j = 0; j < 8; j++) {
            int cc = n0 / 2 + 4 * j + (lane & 3);
            float2 bv = __ldg(&b2p[cc]);
            float2 v0 = make_float2(acc[mt][j][0] + bv.x,
                                    acc[mt][j][1] + bv.y);
            float2 v1 = make_float2(acc[mt][j][2] + bv.x,
                                    acc[mt][j][3] + bv.y);
            o2[r0 * 128 + cc]       = v0;
            o2[(r0 + 8) * 128 + cc] = v1;
        }
    }
}

// ---------------------------------------------------------------------------
extern "C" void kernel_launch(void* const* d_in, const int* in_sizes, int n_in,
                              void* d_out, int out_size) {
    const unsigned int* hap    = (const unsigned int*)d_in[0];
    const float*        tables = (const float*)d_in[1];
    const float*        W1     = (const float*)d_in[2];
    const float*        b1     = (const float*)d_in[3];
    const float*        W2     = (const float*)d_in[4];
    const float*        b2     = (const float*)d_in[5];
    float*              out    = (float*)d_out;

    detect_kernel<<<1, 32>>>(hap);
    precompute_kernel<<<L_ * 32, 512>>>(tables, W1);
    main_kernel<<<NBLK, 256>>>(hap, b1, W2, b2, out);
}

// round 5
// speedup vs baseline: 3.6739x; 1.4445x over previous
#include <cuda_runtime.h>
#include <cuda_fp16.h>
#include <math.h>
#include <stdint.h>

// ---------------------------------------------------------------------------
// HaplotypeEmbedding, fp16 datapath + mma.sync m16n8k16 (fp32 accum).
//   P[l][v][:]  = tables[l][v] @ W1_l   stored fp16 (4.2 MB, L2-resident)
//   W2T[n][k]   = W2[k][n]              stored fp16 (256 KB)
//   Block = 64 samples; 8 k-chunks of 64:
//     all warps: gather+sum(fp32) P + b1 + gelu -> fp16 A[64][64] smem
//                stage W2T chunk                -> fp16 B[256][64] smem
//     all warps: mma m16n8k16 (warp tile 32x64), 64 fp32 acc regs
// ---------------------------------------------------------------------------

#define L_    8
#define V_    512
#define D_    256
#define HID_  512
#define NOUT_ 256
#define NTOT  131072
#define MTILE 64
#define NBLK  (NTOT / MTILE)   // 2048
#define KCH   64
#define NCH   (HID_ / KCH)     // 8

#define SAH 72                 // A stride in halves (36 words = 4 mod 32)
#define SBH 72                 // B stride in halves

__device__ __half g_Ph[L_ * V_ * HID_];    // 4.19 MB
__device__ __half g_W2T[NOUT_ * HID_];     // 256 KB, [n][k]
__device__ int    g_is64;

__device__ __forceinline__ float gelu1(float x) {
    return 0.5f * x * (1.0f + erff(x * 0.70710678118654752440f));
}
__device__ __forceinline__ void mma_f16(float* d, const uint32_t* a,
                                        uint32_t b0, uint32_t b1) {
    asm volatile(
        "mma.sync.aligned.m16n8k16.row.col.f32.f16.f16.f32 "
        "{%0,%1,%2,%3}, {%4,%5,%6,%7}, {%8,%9}, {%0,%1,%2,%3};"
        : "+f"(d[0]), "+f"(d[1]), "+f"(d[2]), "+f"(d[3])
        : "r"(a[0]), "r"(a[1]), "r"(a[2]), "r"(a[3]), "r"(b0), "r"(b1));
}

// ---------------------------------------------------------------------------
__global__ void detect_kernel(const unsigned int* __restrict__ w) {
    if (threadIdx.x == 0) {
        int ok = 1;
        for (int i = 0; i < 64; i++) ok &= (w[2 * i + 1] == 0u);
        g_is64 = ok;
    }
}

// P[l][v][:] = tables[l][v] @ W1_l  -> fp16
__global__ void __launch_bounds__(512) precompute_kernel(
        const float* __restrict__ tables, const float* __restrict__ W1) {
    __shared__ float4 sT4[16 * 64];
    const int l  = blockIdx.x >> 5;
    const int v0 = (blockIdx.x & 31) << 4;
    const int j  = threadIdx.x;

    const float4* tsrc = (const float4*)(tables + (l * V_ + v0) * D_);
    sT4[j]       = tsrc[j];
    sT4[j + 512] = tsrc[j + 512];
    __syncthreads();

    float acc[16];
#pragma unroll
    for (int r = 0; r < 16; r++) acc[r] = 0.f;
    const float* w1p = W1 + (l * D_) * HID_ + j;
#pragma unroll 4
    for (int dq = 0; dq < 64; dq++) {
        float w0 = w1p[(4 * dq + 0) * HID_];
        float w1 = w1p[(4 * dq + 1) * HID_];
        float w2 = w1p[(4 * dq + 2) * HID_];
        float w3 = w1p[(4 * dq + 3) * HID_];
#pragma unroll
        for (int r = 0; r < 16; r++) {
            float4 t = sT4[r * 64 + dq];
            acc[r] += w0 * t.x; acc[r] += w1 * t.y;
            acc[r] += w2 * t.z; acc[r] += w3 * t.w;
        }
    }
#pragma unroll
    for (int r = 0; r < 16; r++)
        g_Ph[(l * V_ + v0 + r) * HID_ + j] = __float2half_rn(acc[r]);
}

// W2T[n][k] = fp16(W2[k][n])
__global__ void __launch_bounds__(256) transpose_w2(const float* __restrict__ W2) {
    int idx = blockIdx.x * 256 + threadIdx.x;   // 512*256
    int k = idx >> 8, n = idx & 255;
    g_W2T[n * HID_ + k] = __float2half_rn(W2[idx]);
}

// ---------------------------------------------------------------------------
__global__ void __launch_bounds__(256, 2) main_kernel(
        const unsigned int* __restrict__ hap,
        const float* __restrict__ b1,
        const float* __restrict__ b2,
        float* __restrict__ out) {
    __shared__ int    sTok[MTILE * L_];     // 2 KB
    __shared__ __half sA[MTILE * SAH];      // 9 KB
    __shared__ __half sB[NOUT_ * SBH];      // 36 KB

    const int tid = threadIdx.x, warp = tid >> 5, lane = tid & 31;
    const int is64 = g_is64;

    // tokens (clamped)
    {
        long gbase = (long)blockIdx.x * (MTILE * L_);
#pragma unroll
        for (int i = 0; i < 2; i++) {
            int idx = tid + 256 * i;
            long gi = gbase + idx;
            int v = is64 ? (int)hap[2 * gi] : (int)hap[gi];
            v = v < 0 ? 0 : (v > V_ - 1 ? V_ - 1 : v);
            sTok[idx] = v;
        }
    }

    float acc[2][8][4];
#pragma unroll
    for (int mt = 0; mt < 2; mt++)
#pragma unroll
        for (int j = 0; j < 8; j++)
#pragma unroll
            for (int q = 0; q < 4; q++) acc[mt][j][q] = 0.f;

    const int c  = lane & 7;            // 8-half group within chunk
    const int r  = lane >> 3;           // row sub-index 0..3
    const int m0 = (warp >> 2) * 32;    // consumer row base
    const int n0 = (warp & 3) * 64;     // consumer col base
    const int bn = tid >> 3;            // staging n row 0..31
    const int bc = tid & 7;

    __syncthreads();

    for (int kt = 0; kt < NCH; kt++) {
        const int k0 = kt * KCH;
        // ---- produce A: gelu(sum_l P[l][tok] + b1), 8 halves/thread/iter ----
        const float4* b1f4 = (const float4*)(b1 + k0);
        float4 bva = __ldg(b1f4 + c * 2);
        float4 bvb = __ldg(b1f4 + c * 2 + 1);
#pragma unroll
        for (int it = 0; it < 2; it++) {
            int m = it * 32 + warp * 4 + r;
            const int* tk = sTok + m * L_;
            float2 a0 = make_float2(0.f, 0.f), a1 = a0, a2 = a0, a3 = a0;
#pragma unroll
            for (int l = 0; l < L_; l++) {
                const uint4 v = *(const uint4*)(g_Ph +
                        (((l * V_ + tk[l]) << 9) + k0 + c * 8));
                float2 p;
                p = __half22float2(*(const __half2*)&v.x); a0.x += p.x; a0.y += p.y;
                p = __half22float2(*(const __half2*)&v.y); a1.x += p.x; a1.y += p.y;
                p = __half22float2(*(const __half2*)&v.z); a2.x += p.x; a2.y += p.y;
                p = __half22float2(*(const __half2*)&v.w); a3.x += p.x; a3.y += p.y;
            }
            __half2 h0 = __floats2half2_rn(gelu1(a0.x + bva.x), gelu1(a0.y + bva.y));
            __half2 h1 = __floats2half2_rn(gelu1(a1.x + bva.z), gelu1(a1.y + bva.w));
            __half2 h2 = __floats2half2_rn(gelu1(a2.x + bvb.x), gelu1(a2.y + bvb.y));
            __half2 h3 = __floats2half2_rn(gelu1(a3.x + bvb.z), gelu1(a3.y + bvb.w));
            uint4 pk;
            pk.x = *(uint32_t*)&h0; pk.y = *(uint32_t*)&h1;
            pk.z = *(uint32_t*)&h2; pk.w = *(uint32_t*)&h3;
            *(uint4*)(sA + m * SAH + c * 8) = pk;
        }
        // ---- produce B: W2T chunk, uint4 coalesced ----
#pragma unroll
        for (int i = 0; i < 8; i++) {
            int n = bn + i * 32;
            uint4 v = *(const uint4*)(g_W2T + n * HID_ + k0 + bc * 8);
            *(uint4*)(sB + n * SBH + bc * 8) = v;
        }
        __syncthreads();

        // ---- consume: warp tile 32x64, 4 k16-steps ----
#pragma unroll
        for (int ks = 0; ks < 4; ks++) {
            const int kb = ks * 16 + (lane & 3) * 2;
            uint32_t a[2][4];
#pragma unroll
            for (int mt = 0; mt < 2; mt++) {
                const __half* Ab = sA + (m0 + mt * 16 + (lane >> 2)) * SAH;
                a[mt][0] = *(const uint32_t*)(Ab + kb);
                a[mt][1] = *(const uint32_t*)(Ab + 8 * SAH + kb);
                a[mt][2] = *(const uint32_t*)(Ab + kb + 8);
                a[mt][3] = *(const uint32_t*)(Ab + 8 * SAH + kb + 8);
            }
            const __half* Bk = sB + (n0 + (lane >> 2)) * SBH + kb;
#pragma unroll
            for (int j = 0; j < 8; j++) {
                uint32_t b0 = *(const uint32_t*)(Bk + 8 * j * SBH);
                uint32_t b1r = *(const uint32_t*)(Bk + 8 * j * SBH + 8);
                mma_f16(acc[0][j], a[0], b0, b1r);
                mma_f16(acc[1][j], a[1], b0, b1r);
            }
        }
        __syncthreads();
    }

    // ---- epilogue: + b2, store ----
    const float2* b2p = (const float2*)b2;
    float2* o2 = (float2*)out;
#pragma unroll
    for (int mt = 0; mt < 2; mt++) {
        size_t r0 = (size_t)blockIdx.x * MTILE + m0 + mt * 16 + (lane >> 2);
#pragma unroll
        for (int j = 0; j < 8; j++) {
            int cc = n0 / 2 + 4 * j + (lane & 3);
            float2 bv = __ldg(&b2p[cc]);
            float2 v0 = make_float2(acc[mt][j][0] + bv.x,
                                    acc[mt][j][1] + bv.y);
            float2 v1 = make_float2(acc[mt][j][2] + bv.x,
                                    acc[mt][j][3] + bv.y);
            o2[r0 * 128 + cc]       = v0;
            o2[(r0 + 8) * 128 + cc] = v1;
        }
    }
}

// ---------------------------------------------------------------------------
extern "C" void kernel_launch(void* const* d_in, const int* in_sizes, int n_in,
                              void* d_out, int out_size) {
    const unsigned int* hap    = (const unsigned int*)d_in[0];
    const float*        tables = (const float*)d_in[1];
    const float*        W1     = (const float*)d_in[2];
    const float*        b1     = (const float*)d_in[3];
    const float*        W2     = (const float*)d_in[4];
    const float*        b2     = (const float*)d_in[5];
    float*              out    = (float*)d_out;

    detect_kernel<<<1, 32>>>(hap);
    precompute_kernel<<<L_ * 32, 512>>>(tables, W1);
    transpose_w2<<<HID_ * NOUT_ / 256, 256>>>(W2);
    main_kernel<<<NBLK, 256>>>(hap, b1, b2, out);
}

// round 6
// speedup vs baseline: 3.9554x; 1.0766x over previous
#include <cuda_runtime.h>
#include <cuda_fp16.h>
#include <math.h>
#include <stdint.h>

// ---------------------------------------------------------------------------
// HaplotypeEmbedding, fp16 datapath + mma.sync m16n8k16 + ldmatrix,
// double-buffered smem, fused prolog.
//   P[l][v][:]  = tables[l][v] @ W1_l   fp16 (4.2 MB, L2-resident)
//   W2T[n][k]   = W2[k][n]              fp16 (256 KB)
//   Block = 64 samples; 8 k-chunks of 64, produce(kt+1) overlapped with
//   consume(kt), one barrier per chunk.
// ---------------------------------------------------------------------------

#define L_    8
#define V_    512
#define D_    256
#define HID_  512
#define NOUT_ 256
#define NTOT  131072
#define MTILE 64
#define NBLK  (NTOT / MTILE)   // 2048
#define KCH   64
#define NCH   (HID_ / KCH)     // 8

#define SAH 72                 // A stride (halves); 144B rows -> LDSM conflict-free
#define SBH 72                 // B stride (halves)
#define SA_BUFH (MTILE * SAH)  // 4608 halves
#define SB_BUFH (NOUT_ * SBH)  // 18432 halves

#define SM_TOK_B 0
#define SM_A_B   2048
#define SM_B_B   (SM_A_B + 2 * SA_BUFH * 2)     // 20480
#define SMEM_BYTES (SM_B_B + 2 * SB_BUFH * 2)   // 94208

__device__ __half g_Ph[L_ * V_ * HID_];
__device__ __half g_W2T[NOUT_ * HID_];
__device__ int    g_is64;

__device__ __forceinline__ float gelu1(float x) {
    return 0.5f * x * (1.0f + erff(x * 0.70710678118654752440f));
}
__device__ __forceinline__ void mma_f16(float* d, const uint32_t* a,
                                        uint32_t b0, uint32_t b1) {
    asm volatile(
        "mma.sync.aligned.m16n8k16.row.col.f32.f16.f16.f32 "
        "{%0,%1,%2,%3}, {%4,%5,%6,%7}, {%8,%9}, {%0,%1,%2,%3};"
        : "+f"(d[0]), "+f"(d[1]), "+f"(d[2]), "+f"(d[3])
        : "r"(a[0]), "r"(a[1]), "r"(a[2]), "r"(a[3]), "r"(b0), "r"(b1));
}
__device__ __forceinline__ void ldsm4(uint32_t& r0, uint32_t& r1,
                                      uint32_t& r2, uint32_t& r3, uint32_t a) {
    asm volatile("ldmatrix.sync.aligned.m8n8.x4.shared.b16 {%0,%1,%2,%3}, [%4];"
                 : "=r"(r0), "=r"(r1), "=r"(r2), "=r"(r3) : "r"(a));
}

// ---------------------------------------------------------------------------
// Fused prolog: P projection + W2 transpose + dtype detect.
// Grid 256 x 512 threads; thread gidx also handles one W2 element.
__global__ void __launch_bounds__(512) precompute_kernel(
        const float* __restrict__ tables, const float* __restrict__ W1,
        const float* __restrict__ W2, const unsigned int* __restrict__ hap) {
    __shared__ float4 sT4[16 * 64];
    const int l  = blockIdx.x >> 5;
    const int v0 = (blockIdx.x & 31) << 4;
    const int j  = threadIdx.x;

    // W2T (one element per thread across the grid)
    {
        int gidx = blockIdx.x * 512 + j;        // 131072 = 512*256
        int k = gidx >> 8, n = gidx & 255;
        g_W2T[n * HID_ + k] = __float2half_rn(W2[gidx]);
    }
    // dtype detect
    if (blockIdx.x == 0 && j == 0) {
        int ok = 1;
        for (int i = 0; i < 64; i++) ok &= (hap[2 * i + 1] == 0u);
        g_is64 = ok;
    }

    const float4* tsrc = (const float4*)(tables + (l * V_ + v0) * D_);
    sT4[j]       = tsrc[j];
    sT4[j + 512] = tsrc[j + 512];
    __syncthreads();

    float acc[16];
#pragma unroll
    for (int r = 0; r < 16; r++) acc[r] = 0.f;
    const float* w1p = W1 + (l * D_) * HID_ + j;
#pragma unroll 4
    for (int dq = 0; dq < 64; dq++) {
        float w0 = w1p[(4 * dq + 0) * HID_];
        float w1 = w1p[(4 * dq + 1) * HID_];
        float w2 = w1p[(4 * dq + 2) * HID_];
        float w3 = w1p[(4 * dq + 3) * HID_];
#pragma unroll
        for (int r = 0; r < 16; r++) {
            float4 t = sT4[r * 64 + dq];
            acc[r] += w0 * t.x; acc[r] += w1 * t.y;
            acc[r] += w2 * t.z; acc[r] += w3 * t.w;
        }
    }
#pragma unroll
    for (int r = 0; r < 16; r++)
        g_Ph[(l * V_ + v0 + r) * HID_ + j] = __float2half_rn(acc[r]);
}

// ---------------------------------------------------------------------------
__global__ void __launch_bounds__(256, 2) main_kernel(
        const unsigned int* __restrict__ hap,
        const float* __restrict__ b1,
        const float* __restrict__ b2,
        float* __restrict__ out) {
    extern __shared__ char smem[];
    int*    sTok = (int*)(smem + SM_TOK_B);
    __half* sA   = (__half*)(smem + SM_A_B);
    __half* sB   = (__half*)(smem + SM_B_B);
    const uint32_t sbA = (uint32_t)__cvta_generic_to_shared(sA);
    const uint32_t sbB = (uint32_t)__cvta_generic_to_shared(sB);

    const int tid = threadIdx.x, warp = tid >> 5, lane = tid & 31;
    const int is64 = g_is64;

    // tokens (clamped)
    {
        long gbase = (long)blockIdx.x * (MTILE * L_);
#pragma unroll
        for (int i = 0; i < 2; i++) {
            int idx = tid + 256 * i;
            long gi = gbase + idx;
            int v = is64 ? (int)hap[2 * gi] : (int)hap[gi];
            v = v < 0 ? 0 : (v > V_ - 1 ? V_ - 1 : v);
            sTok[idx] = v;
        }
    }

    float acc[2][8][4];
#pragma unroll
    for (int mt = 0; mt < 2; mt++)
#pragma unroll
        for (int j = 0; j < 8; j++)
#pragma unroll
            for (int q = 0; q < 4; q++) acc[mt][j][q] = 0.f;

    const int c  = lane & 7;            // 16B segment (producer)
    const int r  = lane >> 3;           // row sub-index (producer)
    const int m0 = (warp >> 2) * 32;    // consumer row base
    const int n0 = (warp & 3) * 64;     // consumer col base
    const int bn = tid >> 3;            // B-stage row
    const int bc = tid & 7;

    // ldmatrix per-lane base offsets (bytes)
    const uint32_t aoff0 = ((uint32_t)(m0 + ((lane >> 3) & 1) * 8 + (lane & 7)) * SAH +
                            (uint32_t)(lane >> 4) * 8) * 2;
    const uint32_t boff0 = ((uint32_t)(n0 + (lane >> 4) * 8 + (lane & 7)) * SBH +
                            (uint32_t)((lane >> 3) & 1) * 8) * 2;

    __syncthreads();

    // ---------------- producer ----------------
    auto produce = [&](int kt, int buf) {
        const int k0 = kt * KCH;
        __half* A = sA + buf * SA_BUFH;
        __half* B = sB + buf * SB_BUFH;
        // B: W2T chunk
#pragma unroll
        for (int i = 0; i < 8; i++) {
            int n = bn + i * 32;
            uint4 v = *(const uint4*)(g_W2T + n * HID_ + k0 + bc * 8);
            *(uint4*)(B + n * SBH + bc * 8) = v;
        }
        // A: gelu(sum_l P + b1)
        const float4* b1f4 = (const float4*)(b1 + k0);
        float4 bva = __ldg(b1f4 + c * 2);
        float4 bvb = __ldg(b1f4 + c * 2 + 1);
#pragma unroll
        for (int it = 0; it < 2; it++) {
            int m = it * 32 + warp * 4 + r;
            const int* tk = sTok + m * L_;
            float2 a0 = make_float2(0.f, 0.f), a1 = a0, a2 = a0, a3 = a0;
#pragma unroll
            for (int lp = 0; lp < 4; lp++) {
                const uint4 u = *(const uint4*)(g_Ph +
                        (((2 * lp) * V_ + tk[2 * lp]) << 9) + k0 + c * 8);
                const uint4 w = *(const uint4*)(g_Ph +
                        (((2 * lp + 1) * V_ + tk[2 * lp + 1]) << 9) + k0 + c * 8);
                __half2 t; float2 p;
                t = __hadd2(*(const __half2*)&u.x, *(const __half2*)&w.x);
                p = __half22float2(t); a0.x += p.x; a0.y += p.y;
                t = __hadd2(*(const __half2*)&u.y, *(const __half2*)&w.y);
                p = __half22float2(t); a1.x += p.x; a1.y += p.y;
                t = __hadd2(*(const __half2*)&u.z, *(const __half2*)&w.z);
                p = __half22float2(t); a2.x += p.x; a2.y += p.y;
                t = __hadd2(*(const __half2*)&u.w, *(const __half2*)&w.w);
                p = __half22float2(t); a3.x += p.x; a3.y += p.y;
            }
            __half2 h0 = __floats2half2_rn(gelu1(a0.x + bva.x), gelu1(a0.y + bva.y));
            __half2 h1 = __floats2half2_rn(gelu1(a1.x + bva.z), gelu1(a1.y + bva.w));
            __half2 h2 = __floats2half2_rn(gelu1(a2.x + bvb.x), gelu1(a2.y + bvb.y));
            __half2 h3 = __floats2half2_rn(gelu1(a3.x + bvb.z), gelu1(a3.y + bvb.w));
            uint4 pk;
            pk.x = *(uint32_t*)&h0; pk.y = *(uint32_t*)&h1;
            pk.z = *(uint32_t*)&h2; pk.w = *(uint32_t*)&h3;
            *(uint4*)(A + m * SAH + c * 8) = pk;
        }
    };

    // ---------------- consumer ----------------
    auto consume = [&](int buf) {
        const uint32_t aB = sbA + buf * SA_BUFH * 2 + aoff0;
        const uint32_t bB = sbB + buf * SB_BUFH * 2 + boff0;
#pragma unroll
        for (int ks = 0; ks < 4; ks++) {
            uint32_t a[2][4];
#pragma unroll
            for (int mt = 0; mt < 2; mt++)
                ldsm4(a[mt][0], a[mt][1], a[mt][2], a[mt][3],
                      aB + (uint32_t)(mt * 16 * SAH * 2) + (uint32_t)(ks * 32));
#pragma unroll
            for (int jp = 0; jp < 4; jp++) {
                uint32_t b0, b1r, b2r, b3r;
                ldsm4(b0, b1r, b2r, b3r,
                      bB + (uint32_t)(jp * 16 * SBH * 2) + (uint32_t)(ks * 32));
                mma_f16(acc[0][2 * jp],     a[0], b0, b1r);
                mma_f16(acc[1][2 * jp],     a[1], b0, b1r);
                mma_f16(acc[0][2 * jp + 1], a[0], b2r, b3r);
                mma_f16(acc[1][2 * jp + 1], a[1], b2r, b3r);
            }
        }
    };

    // ---------------- pipeline: 1 barrier per chunk ----------------
    produce(0, 0);
    __syncthreads();
#pragma unroll 1
    for (int kt = 0; kt < NCH; kt++) {
        const int buf = kt & 1;
        if (kt + 1 < NCH) produce(kt + 1, buf ^ 1);
        consume(buf);
        __syncthreads();
    }

    // ---------------- epilogue: + b2, store ----------------
    const float2* b2p = (const float2*)b2;
    float2* o2 = (float2*)out;
#pragma unroll
    for (int mt = 0; mt < 2; mt++) {
        size_t r0 = (size_t)blockIdx.x * MTILE + m0 + mt * 16 + (lane >> 2);
#pragma unroll
        for (int j = 0; j < 8; j++) {
            int cc = n0 / 2 + 4 * j + (lane & 3);
            float2 bv = __ldg(&b2p[cc]);
            float2 v0 = make_float2(acc[mt][j][0] + bv.x,
                                    acc[mt][j][1] + bv.y);
            float2 v1 = make_float2(acc[mt][j][2] + bv.x,
                                    acc[mt][j][3] + bv.y);
            o2[r0 * 128 + cc]       = v0;
            o2[(r0 + 8) * 128 + cc] = v1;
        }
    }
}

// ---------------------------------------------------------------------------
extern "C" void kernel_launch(void* const* d_in, const int* in_sizes, int n_in,
                              void* d_out, int out_size) {
    const unsigned int* hap    = (const unsigned int*)d_in[0];
    const float*        tables = (const float*)d_in[1];
    const float*        W1     = (const float*)d_in[2];
    const float*        b1     = (const float*)d_in[3];
    const float*        W2     = (const float*)d_in[4];
    const float*        b2     = (const float*)d_in[5];
    float*              out    = (float*)d_out;

    cudaFuncSetAttribute(main_kernel,
                         cudaFuncAttributeMaxDynamicSharedMemorySize, SMEM_BYTES);

    precompute_kernel<<<L_ * 32, 512>>>(tables, W1, W2, hap);
    main_kernel<<<NBLK, 256, SMEM_BYTES>>>(hap, b1, b2, out);
}